// round 16
// baseline (speedup 1.0000x reference)
#include <cuda_runtime.h>
#include <cstdint>

typedef unsigned long long ull;
#define FULLMASK 0xffffffffu

constexpr int MAX_ITER = 8192;
constexpr int NNODES   = MAX_ITER + 1;   // 8193
constexpr int NBLK     = 256;            // 32 iterations per block
constexpr int NTHREADS = 1024;           // 32 warps
constexpr int CSIZE    = 16;             // non-portable cluster size
constexpr int SERIAL_WARP = 31;

constexpr int NODES_PAD = 8208;          // 8193 + sentinel pad (scan reads < 8208)
constexpr int NSLOT_PAD = 34;            // 0..30 samples, 31/32 = sample-31 halves

// per-CTA smem layout:
//   nodes float2[8208] | samps float2[8192] | bests ull[4][16][34]
//   stage ull[4][34] | cand float2[2][32]
//   mbars ull[12]: [0..3]=nodes ring, [4..7]=bests objs, [8..11]=free objs
constexpr size_t OFF_SAMPS = (size_t)NODES_PAD * sizeof(float2);
constexpr size_t OFF_BESTS = OFF_SAMPS + (size_t)MAX_ITER * sizeof(float2);
constexpr size_t OFF_STAGE = OFF_BESTS + 4ull * CSIZE * NSLOT_PAD * sizeof(ull);
constexpr size_t OFF_CAND  = OFF_STAGE + 4ull * NSLOT_PAD * sizeof(ull);
constexpr size_t OFF_MBARS = OFF_CAND + 64ull * sizeof(float2);
constexpr size_t SMEM_BYTES = OFF_MBARS + 12ull * sizeof(ull);

constexpr ull KEY_INF = ((ull)0x7f800000u << 32);

__device__ __forceinline__ uint32_t smem_u32(const void* p) {
    return (uint32_t)__cvta_generic_to_shared(p);
}
__device__ __forceinline__ uint32_t my_ctarank() {
    uint32_t r; asm("mov.u32 %0, %%cluster_ctarank;" : "=r"(r)); return r;
}
__device__ __forceinline__ uint32_t mapa_u32(uint32_t laddr, uint32_t rank) {
    uint32_t r; asm("mapa.shared::cluster.u32 %0, %1, %2;" : "=r"(r) : "r"(laddr), "r"(rank));
    return r;
}
__device__ __forceinline__ void mbar_init(uint32_t a, uint32_t cnt) {
    asm volatile("mbarrier.init.shared.b64 [%0], %1;" :: "r"(a), "r"(cnt) : "memory");
}
__device__ __forceinline__ void mbar_arrive_cta(uint32_t a) {
    asm volatile("mbarrier.arrive.release.cta.shared::cta.b64 _, [%0];" :: "r"(a) : "memory");
}
__device__ __forceinline__ void mbar_arrive_cluster_remote(uint32_t raddr) {
    asm volatile("mbarrier.arrive.release.cluster.shared::cluster.b64 _, [%0];"
                 :: "r"(raddr) : "memory");
}
__device__ __forceinline__ void mbar_wait_cta(uint32_t a, uint32_t phase) {
    asm volatile(
        "{\n\t.reg .pred P;\n\t"
        "WL_%=:\n\t"
        "mbarrier.try_wait.parity.acquire.cta.shared::cta.b64 P, [%0], %1, 0x989680;\n\t"
        "@P bra.uni WD_%=;\n\t"
        "bra.uni WL_%=;\n\t"
        "WD_%=:\n\t}"
        :: "r"(a), "r"(phase) : "memory");
}
__device__ __forceinline__ void mbar_wait_cluster(uint32_t a, uint32_t phase) {
    asm volatile(
        "{\n\t.reg .pred P;\n\t"
        "WL_%=:\n\t"
        "mbarrier.try_wait.parity.acquire.cluster.shared::cta.b64 P, [%0], %1, 0x989680;\n\t"
        "@P bra.uni WD_%=;\n\t"
        "bra.uni WL_%=;\n\t"
        "WD_%=:\n\t}"
        :: "r"(a), "r"(phase) : "memory");
}
#define CLUSTER_ARRIVE() asm volatile("barrier.cluster.arrive.aligned;" ::: "memory")
#define CLUSTER_WAIT()   asm volatile("barrier.cluster.wait.aligned;"   ::: "memory")
#define SCAN_BAR()       asm volatile("bar.sync 1, 992;" ::: "memory")

__device__ __forceinline__ ull bfly_min(ull key) {
    #pragma unroll
    for (int o = 16; o > 0; o >>= 1) {
        ull other = __shfl_xor_sync(FULLMASK, key, o);
        key = (other < key) ? other : key;
    }
    return key;
}

__device__ __forceinline__ ull umin64(ull a, ull b) { return (b < a) ? b : a; }

__device__ __forceinline__ void steer(float fx, float fy, float sx, float sy, float d2,
                                      float& ox, float& oy) {
    float dist = __fsqrt_rn(__fadd_rn(d2, 1e-12f));
    float q    = __fdiv_rn(5.0f, dist);
    float sc   = (dist > 5.0f) ? q : 1.0f;
    ox = __fadd_rn(fx, __fmul_rn(__fadd_rn(sx, -fx), sc));
    oy = __fadd_rn(fy, __fmul_rn(__fadd_rn(sy, -fy), sc));
}

__device__ __forceinline__ float d2_rn(float nx, float ny, float sx, float sy) {
    float dx = __fadd_rn(nx, -sx), dy = __fadd_rn(ny, -sy);
    return __fadd_rn(__fmul_rn(dx, dx), __fmul_rn(dy, dy));
}

// packed f32x2 distance: per-component IEEE rn => bit-identical to d2_rn
__device__ __forceinline__ float d2_pk(float nx, float ny, ull ns_pk) {
    ull nxy;  asm("mov.b64 %0, {%1, %2};" : "=l"(nxy) : "r"(__float_as_uint(nx)),
                                                        "r"(__float_as_uint(ny)));
    ull diff; asm("add.rn.f32x2 %0, %1, %2;" : "=l"(diff) : "l"(nxy), "l"(ns_pk));
    ull sq;   asm("mul.rn.f32x2 %0, %1, %2;" : "=l"(sq)   : "l"(diff), "l"(diff));
    uint32_t lo, hi;
    asm("mov.b64 {%0, %1}, %2;" : "=r"(lo), "=r"(hi) : "l"(sq));
    return __fadd_rn(__uint_as_float(lo), __uint_as_float(hi));
}

// per-lane scan partial, 128-node tiles; tile-winner tracking + exact
// recompute of the winning tile (first-index tiebreak). Raced keys are TRUE
// (d2,idx) pairs duplicating delta coverage => u64 merges stay exact.
__device__ __forceinline__ ull scan_part(const float2* __restrict__ nodes_s, float2 s,
                                         int bound, int t0, int tstep, int lane) {
    const float INF = __int_as_float(0x7f800000);
    ull ns_pk;   // (-sx, -sy) packed
    asm("mov.b64 %0, {%1, %2};" : "=l"(ns_pk)
        : "r"(__float_as_uint(-s.x)), "r"(__float_as_uint(-s.y)));
    float bd2 = INF; int btile = -1;
    #pragma unroll 2
    for (int t = t0; 128 * t <= bound; t += tstep) {
        int i0 = 128 * t + 2 * lane;
        float4 a = *reinterpret_cast<const float4*>(&nodes_s[i0]);
        float4 c = *reinterpret_cast<const float4*>(&nodes_s[i0 + 64]);
        float da0 = d2_pk(a.x, a.y, ns_pk);
        float da1 = d2_pk(a.z, a.w, ns_pk);
        float dc0 = d2_pk(c.x, c.y, ns_pk);
        float dc1 = d2_pk(c.z, c.w, ns_pk);
        float m = fminf(fminf(da0, da1), fminf(dc0, dc1));
        if (m < bd2) { bd2 = m; btile = t; }     // strict <: earliest tile
    }
    int bidx = 0;
    if (btile >= 0) {
        int i0 = 128 * btile + 2 * lane;
        float4 a = *reinterpret_cast<const float4*>(&nodes_s[i0]);
        float4 c = *reinterpret_cast<const float4*>(&nodes_s[i0 + 64]);
        float da0 = d2_pk(a.x, a.y, ns_pk);
        float da1 = d2_pk(a.z, a.w, ns_pk);
        float dc0 = d2_pk(c.x, c.y, ns_pk);
        float dc1 = d2_pk(c.z, c.w, ns_pk);
        float m01 = fminf(da0, da1); int i01 = (da0 <= da1) ? i0 : i0 + 1;
        float m23 = fminf(dc0, dc1); int i23 = (dc0 <= dc1) ? i0 + 64 : i0 + 65;
        bd2  = fminf(m01, m23);
        bidx = (m01 <= m23) ? i01 : i23;         // lower idx on tie
    }
    return ((ull)__float_as_uint(bd2) << 32) | (uint32_t)bidx;
}

__global__ void __launch_bounds__(NTHREADS, 1)
rrt_kernel(const float* __restrict__ state,
           const float* __restrict__ goal,
           const float* __restrict__ u,
           const float* __restrict__ r,
           float* __restrict__ out)
{
    extern __shared__ char smem_raw[];
    float2* nodes_s = (float2*)smem_raw;
    float2* samps   = (float2*)(smem_raw + OFF_SAMPS);
    ull (*bests)[CSIZE][NSLOT_PAD] = (ull (*)[CSIZE][NSLOT_PAD])(smem_raw + OFF_BESTS);
    ull (*stage)[NSLOT_PAD] = (ull (*)[NSLOT_PAD])(smem_raw + OFF_STAGE);
    float2* cand    = (float2*)(smem_raw + OFF_CAND);   // [2][32] ring
    ull* mbars      = (ull*)(smem_raw + OFF_MBARS);

    const int tid  = threadIdx.x;
    const int lane = tid & 31;
    const int warp = tid >> 5;
    const uint32_t crank = my_ctarank();
    const float INF = __int_as_float(0x7f800000);

    const uint32_t mb_nodes0 = smem_u32(&mbars[0]);   // 4 ring objs at +8*idx
    const uint32_t mb_bests0 = smem_u32(&mbars[4]);   // 4 objs at +8*idx
    const uint32_t mb_free0  = smem_u32(&mbars[8]);   // 4 objs at +8*idx

    // ---- init ----
    for (int i = tid; i < NODES_PAD; i += NTHREADS)
        nodes_s[i] = make_float2(INF, INF);
    const float gx = goal[0], gy = goal[1];
    for (int i = tid; i < MAX_ITER; i += NTHREADS) {
        float ui = u[i];
        float sx = __fmul_rn(r[2 * i],     200.0f);
        float sy = __fmul_rn(r[2 * i + 1], 200.0f);
        if (ui < 0.1f) { sx = gx; sy = gy; }
        samps[i] = make_float2(sx, sy);
    }
    if (tid < 64) cand[tid] = make_float2(INF, INF);   // blocks "-2","-1"
    if (tid < 4 * NSLOT_PAD) ((ull*)stage)[tid] = KEY_INF;
    if (tid == 0) {
        float2 st0 = make_float2(state[0], state[1]);
        nodes_s[0] = st0;
        // block "-1" ring half = parity 1; slot 31 <-> idx 32*0-31+31 = 0 = root
        cand[32 + 31] = st0;
        for (int o = 0; o < 4; o++) {
            mbar_init(mb_nodes0 + 8 * o, 32);          // serial warp lanes
            mbar_init(mb_bests0 + 8 * o, CSIZE);       // ONE arrive per src CTA
            mbar_init(mb_free0  + 8 * o, CSIZE);       // one arrive per dst serial
        }
    }
    __syncthreads();
    CLUSTER_ARRIVE();
    CLUSTER_WAIT();

    for (int b = 0; b < NBLK; b++) {
        if (warp == SERIAL_WARP) {
            // ===== serial warp: fully self-sufficient block b =====
            const float2 s2 = samps[32 * b + lane];
            const float sx = s2.x, sy = s2.y;

            // delta64 over cand ring: older half (block b-2, parity b&1, base 32b-63)
            // then newer half (block b-1, base 32b-31); increasing idx + strict <
            float bd2 = INF; int bidx = 0;
            {
                const float4* oldh = (const float4*)(cand + 32 * (b & 1));
                const float4* newh = (const float4*)(cand + 32 * ((b - 1) & 1));
                #pragma unroll
                for (int l = 0; l < 32; l += 2) {
                    float4 c = oldh[l >> 1];
                    float d0 = d2_rn(c.x, c.y, sx, sy);
                    float d1 = d2_rn(c.z, c.w, sx, sy);
                    if (d0 < bd2) { bd2 = d0; bidx = 32 * b - 63 + l; }
                    if (d1 < bd2) { bd2 = d1; bidx = 32 * b - 63 + l + 1; }
                }
                #pragma unroll
                for (int l = 0; l < 32; l += 2) {
                    float4 c = newh[l >> 1];
                    float d0 = d2_rn(c.x, c.y, sx, sy);
                    float d1 = d2_rn(c.z, c.w, sx, sy);
                    if (d0 < bd2) { bd2 = d0; bidx = 32 * b - 31 + l; }
                    if (d1 < bd2) { bd2 = d1; bidx = 32 * b - 31 + l + 1; }
                }
            }
            // merge bests(b): [0, 32b-64], sent at iteration b-2 (2 blocks slack)
            if (b >= 2) {
                const int obj = (b - 2) & 3;
                mbar_wait_cluster(mb_bests0 + 8 * obj, ((b - 2) >> 2) & 1);
                ull p0 = KEY_INF, p1 = KEY_INF, p2 = KEY_INF, p3 = KEY_INF;
                #pragma unroll
                for (int c = 0; c < CSIZE; c += 4) {   // 4 independent chains
                    p0 = umin64(p0, bests[obj][c + 0][lane]);
                    p1 = umin64(p1, bests[obj][c + 1][lane]);
                    p2 = umin64(p2, bests[obj][c + 2][lane]);
                    p3 = umin64(p3, bests[obj][c + 3][lane]);
                }
                ull kk = umin64(umin64(p0, p1), umin64(p2, p3));
                if (lane == 31) {
                    ull q0 = KEY_INF, q1 = KEY_INF;
                    #pragma unroll
                    for (int c = 0; c < CSIZE; c += 2) {
                        q0 = umin64(q0, bests[obj][c + 0][32]);
                        q1 = umin64(q1, bests[obj][c + 1][32]);
                    }
                    kk = umin64(kk, umin64(q0, q1));
                }
                // release bests[obj] for reuse: one arrive to EVERY CTA's free[obj]
                if (lane < CSIZE)
                    mbar_arrive_cluster_remote(mapa_u32(mb_free0 + 8 * obj,
                                                        (uint32_t)lane));
                ull dk = ((ull)__float_as_uint(bd2) << 32) | (uint32_t)bidx;
                if (kk < dk) {                       // u64: exact (d2, idx) order
                    bd2  = __uint_as_float((uint32_t)(kk >> 32));
                    bidx = (int)(uint32_t)kk;
                }
            }
            float2 f = nodes_s[bidx];
            float cx, cy;
            steer(f.x, f.y, sx, sy, bd2, cx, cy);

            // speculative fixup; working buffer = ring half b&1 (old data consumed)
            float2* wcand = cand + 32 * (b & 1);
            const float4* wcand4 = (const float4*)wcand;
            __syncwarp();                            // delta reads done before overwrite
            while (true) {
                wcand[lane] = make_float2(cx, cy);
                __syncwarp();
                float vmin = INF; int vl = 0;
                #pragma unroll
                for (int l = 0; l < 32; l += 2) {
                    float4 c = wcand4[l >> 1];
                    float e0 = d2_rn(c.x, c.y, sx, sy);
                    float e1 = d2_rn(c.z, c.w, sx, sy);
                    if (l     < lane && e0 < vmin) { vmin = e0; vl = l; }
                    if (l + 1 < lane && e1 < vmin) { vmin = e1; vl = l + 1; }
                }
                unsigned mask = __ballot_sync(FULLMASK, vmin < bd2);   // strict <
                if (!mask) break;
                int F2 = __ffs((int)mask) - 1;       // first violator vs finals only
                if (lane == F2) {
                    bd2 = vmin;
                    float2 c = wcand[vl];
                    steer(c.x, c.y, sx, sy, bd2, cx, cy);
                }
            }
            __syncwarp();
            nodes_s[32 * b + 1 + lane] = make_float2(cx, cy);
            if (b < NBLK - 1)
                mbar_arrive_cta(mb_nodes0 + 8 * (b & 3));   // all 32 lanes
        } else {
            // ===== scan warps (0..30): iteration j = b, entirely off-path =====
            const int j = b;
            if (j > NBLK - 3) continue;               // no consumer remains
            if (j >= 1)                               // nodes [0,32j] final
                mbar_wait_cta(mb_nodes0 + 8 * ((j - 1) & 3), ((j - 1) >> 2) & 1);

            const int obj = j & 3;                    // consumed by serial block j+2
            ull pk = scan_part(nodes_s, samps[32 * (j + 2) + warp],
                               32 * j, (int)crank, CSIZE, lane);
            pk = bfly_min(pk);
            if (lane == 0) stage[obj][warp] = pk;     // local staging
            if (warp == 29 || warp == 30) {           // sample-31 scan split halves
                int t0 = (warp == 29) ? (int)crank : (int)crank + CSIZE;
                ull pk2 = scan_part(nodes_s, samps[32 * (j + 2) + 31],
                                    32 * j, t0, 2 * CSIZE, lane);
                pk2 = bfly_min(pk2);
                int slot = (warp == 29) ? 31 : 32;
                if (lane == 0) stage[obj][slot] = pk2;
            }
            SCAN_BAR();                               // 31 scan warps: staging visible

            // ---- batched cross-CTA send: warp w (w<16) -> CTA w, lane 0 only ----
            if (warp < CSIZE && lane == 0) {
                // backpressure: previous readers of bests[obj] (all dst serials
                // at their block j-2) must have finished before we overwrite
                if (j >= 4)
                    mbar_wait_cluster(mb_free0 + 8 * obj, ((j - 4) >> 2) & 1);
                uint32_t src  = smem_u32(&stage[obj][0]);
                uint32_t dstr = mapa_u32(smem_u32(&bests[obj][crank][0]),
                                         (uint32_t)warp);
                #pragma unroll
                for (int k = 0; k < 17; k++) {        // 34 slots = 17 x 16B
                    ull a0, a1;
                    asm volatile("ld.shared.v2.u64 {%0, %1}, [%2];"
                                 : "=l"(a0), "=l"(a1) : "r"(src + 16 * k));
                    asm volatile("st.shared::cluster.v2.u64 [%0], {%1, %2};"
                                 :: "r"(dstr + 16 * k), "l"(a0), "l"(a1) : "memory");
                }
                mbar_arrive_cluster_remote(mapa_u32(mb_bests0 + 8 * obj,
                                                    (uint32_t)warp));
            }
        }
    }

    __syncthreads();
    CLUSTER_ARRIVE();
    CLUSTER_WAIT();

    if (crank == 0) {
        const float* ns = reinterpret_cast<const float*>(nodes_s);
        for (int i = tid; i < 2 * NNODES; i += NTHREADS)
            out[i] = ns[i];
    }
}

extern "C" void kernel_launch(void* const* d_in, const int* in_sizes, int n_in,
                              void* d_out, int out_size)
{
    const float* state = (const float*)d_in[0];
    const float* goal  = (const float*)d_in[1];
    const float* u     = (const float*)d_in[2];
    const float* r     = (const float*)d_in[3];
    float* out = (float*)d_out;

    cudaFuncSetAttribute(rrt_kernel,
                         cudaFuncAttributeNonPortableClusterSizeAllowed, 1);
    cudaFuncSetAttribute(rrt_kernel,
                         cudaFuncAttributeMaxDynamicSharedMemorySize,
                         (int)SMEM_BYTES);

    cudaLaunchConfig_t cfg = {};
    cfg.gridDim  = dim3(CSIZE, 1, 1);
    cfg.blockDim = dim3(NTHREADS, 1, 1);
    cfg.dynamicSmemBytes = SMEM_BYTES;
    cfg.stream = 0;
    cudaLaunchAttribute attrs[1];
    attrs[0].id = cudaLaunchAttributeClusterDimension;
    attrs[0].val.clusterDim.x = CSIZE;
    attrs[0].val.clusterDim.y = 1;
    attrs[0].val.clusterDim.z = 1;
    cfg.attrs = attrs;
    cfg.numAttrs = 1;

    cudaLaunchKernelEx(&cfg, rrt_kernel, state, goal, u, r, out);
}

// round 17
// speedup vs baseline: 1.0908x; 1.0908x over previous
#include <cuda_runtime.h>
#include <cstdint>

typedef unsigned long long ull;
#define FULLMASK 0xffffffffu

constexpr int MAX_ITER = 8192;
constexpr int NNODES   = MAX_ITER + 1;   // 8193
constexpr int K        = 31;             // iterations per block = #scan warps
constexpr int NBLK     = (MAX_ITER + K - 1) / K;   // 265 (264 full + 8 tail)
constexpr int NTHREADS = 1024;           // 32 warps
constexpr int CSIZE    = 8;
constexpr int SERIAL_WARP = 31;

constexpr int NODES_PAD = 8208;          // 8193 + sentinel pad (scan reads < 8208)
constexpr int NSLOT     = 32;            // 31 samples + 1 pad (KEY_INF forever)

// per-CTA smem layout:
//   nodes float2[8208] | samps float2[8192] | bests ull[4][8][32]
//   stage ull[4][32] | cand float2[2][32]
//   mbars ull[12]: [0..3]=nodes ring, [4..7]=bests objs, [8..11]=free objs
constexpr size_t OFF_SAMPS = (size_t)NODES_PAD * sizeof(float2);
constexpr size_t OFF_BESTS = OFF_SAMPS + (size_t)MAX_ITER * sizeof(float2);
constexpr size_t OFF_STAGE = OFF_BESTS + 4ull * CSIZE * NSLOT * sizeof(ull);
constexpr size_t OFF_CAND  = OFF_STAGE + 4ull * NSLOT * sizeof(ull);
constexpr size_t OFF_MBARS = OFF_CAND + 64ull * sizeof(float2);
constexpr size_t SMEM_BYTES = OFF_MBARS + 12ull * sizeof(ull);

constexpr ull KEY_INF = ((ull)0x7f800000u << 32);

__device__ __forceinline__ uint32_t smem_u32(const void* p) {
    return (uint32_t)__cvta_generic_to_shared(p);
}
__device__ __forceinline__ uint32_t my_ctarank() {
    uint32_t r; asm("mov.u32 %0, %%cluster_ctarank;" : "=r"(r)); return r;
}
__device__ __forceinline__ uint32_t mapa_u32(uint32_t laddr, uint32_t rank) {
    uint32_t r; asm("mapa.shared::cluster.u32 %0, %1, %2;" : "=r"(r) : "r"(laddr), "r"(rank));
    return r;
}
__device__ __forceinline__ void mbar_init(uint32_t a, uint32_t cnt) {
    asm volatile("mbarrier.init.shared.b64 [%0], %1;" :: "r"(a), "r"(cnt) : "memory");
}
__device__ __forceinline__ void mbar_arrive_cta(uint32_t a) {
    asm volatile("mbarrier.arrive.release.cta.shared::cta.b64 _, [%0];" :: "r"(a) : "memory");
}
__device__ __forceinline__ void mbar_arrive_cluster_remote(uint32_t raddr) {
    asm volatile("mbarrier.arrive.release.cluster.shared::cluster.b64 _, [%0];"
                 :: "r"(raddr) : "memory");
}
__device__ __forceinline__ void mbar_wait_cta(uint32_t a, uint32_t phase) {
    asm volatile(
        "{\n\t.reg .pred P;\n\t"
        "WL_%=:\n\t"
        "mbarrier.try_wait.parity.acquire.cta.shared::cta.b64 P, [%0], %1, 0x989680;\n\t"
        "@P bra.uni WD_%=;\n\t"
        "bra.uni WL_%=;\n\t"
        "WD_%=:\n\t}"
        :: "r"(a), "r"(phase) : "memory");
}
__device__ __forceinline__ void mbar_wait_cluster(uint32_t a, uint32_t phase) {
    asm volatile(
        "{\n\t.reg .pred P;\n\t"
        "WL_%=:\n\t"
        "mbarrier.try_wait.parity.acquire.cluster.shared::cta.b64 P, [%0], %1, 0x989680;\n\t"
        "@P bra.uni WD_%=;\n\t"
        "bra.uni WL_%=;\n\t"
        "WD_%=:\n\t}"
        :: "r"(a), "r"(phase) : "memory");
}
#define CLUSTER_ARRIVE() asm volatile("barrier.cluster.arrive.aligned;" ::: "memory")
#define CLUSTER_WAIT()   asm volatile("barrier.cluster.wait.aligned;"   ::: "memory")
#define SCAN_BAR()       asm volatile("bar.sync 1, 992;" ::: "memory")

__device__ __forceinline__ ull bfly_min(ull key) {
    #pragma unroll
    for (int o = 16; o > 0; o >>= 1) {
        ull other = __shfl_xor_sync(FULLMASK, key, o);
        key = (other < key) ? other : key;
    }
    return key;
}

__device__ __forceinline__ ull umin64(ull a, ull b) { return (b < a) ? b : a; }

__device__ __forceinline__ void steer(float fx, float fy, float sx, float sy, float d2,
                                      float& ox, float& oy) {
    float dist = __fsqrt_rn(__fadd_rn(d2, 1e-12f));
    float q    = __fdiv_rn(5.0f, dist);
    float sc   = (dist > 5.0f) ? q : 1.0f;
    ox = __fadd_rn(fx, __fmul_rn(__fadd_rn(sx, -fx), sc));
    oy = __fadd_rn(fy, __fmul_rn(__fadd_rn(sy, -fy), sc));
}

__device__ __forceinline__ float d2_rn(float nx, float ny, float sx, float sy) {
    float dx = __fadd_rn(nx, -sx), dy = __fadd_rn(ny, -sy);
    return __fadd_rn(__fmul_rn(dx, dx), __fmul_rn(dy, dy));
}

// packed f32x2 distance: per-component IEEE rn => bit-identical to d2_rn
__device__ __forceinline__ float d2_pk(float nx, float ny, ull ns_pk) {
    ull nxy;  asm("mov.b64 %0, {%1, %2};" : "=l"(nxy) : "r"(__float_as_uint(nx)),
                                                        "r"(__float_as_uint(ny)));
    ull diff; asm("add.rn.f32x2 %0, %1, %2;" : "=l"(diff) : "l"(nxy), "l"(ns_pk));
    ull sq;   asm("mul.rn.f32x2 %0, %1, %2;" : "=l"(sq)   : "l"(diff), "l"(diff));
    uint32_t lo, hi;
    asm("mov.b64 {%0, %1}, %2;" : "=r"(lo), "=r"(hi) : "l"(sq));
    return __fadd_rn(__uint_as_float(lo), __uint_as_float(hi));
}

// per-lane scan partial, 128-node tiles; tile-winner tracking + exact
// recompute of the winning tile (first-index tiebreak). Raced keys are TRUE
// (d2,idx) pairs duplicating delta coverage => u64 merges stay exact.
__device__ __forceinline__ ull scan_part(const float2* __restrict__ nodes_s, float2 s,
                                         int bound, int t0, int tstep, int lane) {
    const float INF = __int_as_float(0x7f800000);
    ull ns_pk;   // (-sx, -sy) packed
    asm("mov.b64 %0, {%1, %2};" : "=l"(ns_pk)
        : "r"(__float_as_uint(-s.x)), "r"(__float_as_uint(-s.y)));
    float bd2 = INF; int btile = -1;
    #pragma unroll 2
    for (int t = t0; 128 * t <= bound; t += tstep) {
        int i0 = 128 * t + 2 * lane;
        float4 a = *reinterpret_cast<const float4*>(&nodes_s[i0]);
        float4 c = *reinterpret_cast<const float4*>(&nodes_s[i0 + 64]);
        float da0 = d2_pk(a.x, a.y, ns_pk);
        float da1 = d2_pk(a.z, a.w, ns_pk);
        float dc0 = d2_pk(c.x, c.y, ns_pk);
        float dc1 = d2_pk(c.z, c.w, ns_pk);
        float m = fminf(fminf(da0, da1), fminf(dc0, dc1));
        if (m < bd2) { bd2 = m; btile = t; }     // strict <: earliest tile
    }
    int bidx = 0;
    if (btile >= 0) {
        int i0 = 128 * btile + 2 * lane;
        float4 a = *reinterpret_cast<const float4*>(&nodes_s[i0]);
        float4 c = *reinterpret_cast<const float4*>(&nodes_s[i0 + 64]);
        float da0 = d2_pk(a.x, a.y, ns_pk);
        float da1 = d2_pk(a.z, a.w, ns_pk);
        float dc0 = d2_pk(c.x, c.y, ns_pk);
        float dc1 = d2_pk(c.z, c.w, ns_pk);
        float m01 = fminf(da0, da1); int i01 = (da0 <= da1) ? i0 : i0 + 1;
        float m23 = fminf(dc0, dc1); int i23 = (dc0 <= dc1) ? i0 + 64 : i0 + 65;
        bd2  = fminf(m01, m23);
        bidx = (m01 <= m23) ? i01 : i23;         // lower idx on tie
    }
    return ((ull)__float_as_uint(bd2) << 32) | (uint32_t)bidx;
}

__global__ void __launch_bounds__(NTHREADS, 1) __cluster_dims__(CSIZE, 1, 1)
rrt_kernel(const float* __restrict__ state,
           const float* __restrict__ goal,
           const float* __restrict__ u,
           const float* __restrict__ r,
           float* __restrict__ out)
{
    extern __shared__ char smem_raw[];
    float2* nodes_s = (float2*)smem_raw;
    float2* samps   = (float2*)(smem_raw + OFF_SAMPS);
    ull (*bests)[CSIZE][NSLOT] = (ull (*)[CSIZE][NSLOT])(smem_raw + OFF_BESTS);
    ull (*stage)[NSLOT] = (ull (*)[NSLOT])(smem_raw + OFF_STAGE);
    float2* cand    = (float2*)(smem_raw + OFF_CAND);   // [2][32] ring
    ull* mbars      = (ull*)(smem_raw + OFF_MBARS);

    const int tid  = threadIdx.x;
    const int lane = tid & 31;
    const int warp = tid >> 5;
    const uint32_t crank = my_ctarank();
    const float INF = __int_as_float(0x7f800000);

    const uint32_t mb_nodes0 = smem_u32(&mbars[0]);   // 4 ring objs at +8*idx
    const uint32_t mb_bests0 = smem_u32(&mbars[4]);   // 4 objs at +8*idx
    const uint32_t mb_free0  = smem_u32(&mbars[8]);   // 4 objs at +8*idx

    // ---- init ----
    for (int i = tid; i < NODES_PAD; i += NTHREADS)
        nodes_s[i] = make_float2(INF, INF);
    const float gx = goal[0], gy = goal[1];
    for (int i = tid; i < MAX_ITER; i += NTHREADS) {
        float ui = u[i];
        float sx = __fmul_rn(r[2 * i],     200.0f);
        float sy = __fmul_rn(r[2 * i + 1], 200.0f);
        if (ui < 0.1f) { sx = gx; sy = gy; }
        samps[i] = make_float2(sx, sy);
    }
    if (tid < 64) cand[tid] = make_float2(INF, INF);   // blocks "-2","-1"
    if (tid < 4 * NSLOT) ((ull*)stage)[tid] = KEY_INF; // pad slot 31 stays INF
    if (tid == 0) {
        float2 st0 = make_float2(state[0], state[1]);
        nodes_s[0] = st0;
        // block "-1" = ring half parity 1; entry 30 <-> idx 31*0-30+30 = 0 = root
        cand[32 + 30] = st0;
        for (int o = 0; o < 4; o++) {
            mbar_init(mb_nodes0 + 8 * o, 32);          // serial warp lanes
            mbar_init(mb_bests0 + 8 * o, CSIZE);       // ONE arrive per src CTA
            mbar_init(mb_free0  + 8 * o, CSIZE);       // one arrive per dst serial
        }
    }
    __syncthreads();
    CLUSTER_ARRIVE();
    CLUSTER_WAIT();

    for (int b = 0; b < NBLK; b++) {
        if (warp == SERIAL_WARP) {
            // ===== serial warp: block b, samples 31b..31b+30 (lane<31) =====
            const int sidx = K * b + lane;
            const bool active = (lane < K) && (sidx < MAX_ITER);
            const float2 s2 = samps[active ? sidx : 0];
            const float sx = s2.x, sy = s2.y;

            // ---- hoisted bests(b) wait + loads (LDS hides under delta) ----
            ull kk = KEY_INF;
            if (b >= 2) {
                const int obj = (b - 2) & 3;
                mbar_wait_cluster(mb_bests0 + 8 * obj, ((b - 2) >> 2) & 1);
                ull p0 = umin64(bests[obj][0][lane], bests[obj][1][lane]);
                ull p1 = umin64(bests[obj][2][lane], bests[obj][3][lane]);
                ull p2 = umin64(bests[obj][4][lane], bests[obj][5][lane]);
                ull p3 = umin64(bests[obj][6][lane], bests[obj][7][lane]);
                kk = umin64(umin64(p0, p1), umin64(p2, p3));
                // release bests[obj] for reuse: one arrive to EVERY CTA's free[obj]
                if (lane < CSIZE)
                    mbar_arrive_cluster_remote(mapa_u32(mb_free0 + 8 * obj,
                                                        (uint32_t)lane));
            }

            // ---- delta62 over cand ring (entry 31 of each half is INF) ----
            // old half = block b-2 (parity b&1, idx base 31b-61)
            // new half = block b-1 (idx base 31b-30); increasing idx + strict <
            float bd2 = INF; int bidx = 0;
            {
                const float4* oldh = (const float4*)(cand + 32 * (b & 1));
                const float4* newh = (const float4*)(cand + 32 * ((b - 1) & 1));
                #pragma unroll
                for (int l = 0; l < 32; l += 2) {
                    float4 c = oldh[l >> 1];
                    float d0 = d2_rn(c.x, c.y, sx, sy);
                    float d1 = d2_rn(c.z, c.w, sx, sy);
                    if (d0 < bd2) { bd2 = d0; bidx = K * b - 61 + l; }
                    if (d1 < bd2) { bd2 = d1; bidx = K * b - 61 + l + 1; }
                }
                #pragma unroll
                for (int l = 0; l < 32; l += 2) {
                    float4 c = newh[l >> 1];
                    float d0 = d2_rn(c.x, c.y, sx, sy);
                    float d1 = d2_rn(c.z, c.w, sx, sy);
                    if (d0 < bd2) { bd2 = d0; bidx = K * b - 30 + l; }
                    if (d1 < bd2) { bd2 = d1; bidx = K * b - 30 + l + 1; }
                }
            }
            // merge bests: idx < delta idx; u64 lexicographic order is exact
            {
                ull dk = ((ull)__float_as_uint(bd2) << 32) | (uint32_t)bidx;
                if (kk < dk) {
                    bd2  = __uint_as_float((uint32_t)(kk >> 32));
                    bidx = (int)(uint32_t)kk;
                }
            }
            float2 f = nodes_s[bidx < 0 ? 0 : bidx];
            float cx, cy;
            steer(f.x, f.y, sx, sy, bd2, cx, cy);
            if (!active) { cx = INF; cy = INF; }

            // ---- speculative fixup; working buffer = ring half b&1 ----
            float2* wcand = cand + 32 * (b & 1);
            const float4* wcand4 = (const float4*)wcand;
            __syncwarp();                            // delta reads done
            while (true) {
                wcand[lane] = make_float2(cx, cy);
                __syncwarp();
                float vmin = INF; int vl = 0;
                #pragma unroll
                for (int l = 0; l < 32; l += 2) {
                    float4 c = wcand4[l >> 1];
                    float e0 = d2_rn(c.x, c.y, sx, sy);
                    float e1 = d2_rn(c.z, c.w, sx, sy);
                    if (l     < lane && e0 < vmin) { vmin = e0; vl = l; }
                    if (l + 1 < lane && e1 < vmin) { vmin = e1; vl = l + 1; }
                }
                if (!active) vmin = INF;
                unsigned mask = __ballot_sync(FULLMASK, vmin < bd2);   // strict <
                if (!mask) break;
                int F2 = __ffs((int)mask) - 1;       // first violator vs finals only
                if (lane == F2) {
                    bd2 = vmin;
                    float2 c = wcand[vl];
                    steer(c.x, c.y, sx, sy, bd2, cx, cy);
                }
            }
            __syncwarp();
            if (active) nodes_s[sidx + 1] = make_float2(cx, cy);
            if (b < NBLK - 1)
                mbar_arrive_cta(mb_nodes0 + 8 * (b & 3));   // all 32 lanes
        } else {
            // ===== scan warps (0..30): iteration j = b, entirely off-path =====
            const int j = b;
            if (j > NBLK - 3) continue;               // no consumer remains
            if (j >= 1)                               // nodes [0,31j] final
                mbar_wait_cta(mb_nodes0 + 8 * ((j - 1) & 3), ((j - 1) >> 2) & 1);

            const int obj = j & 3;                    // consumed by serial block j+2
            const int tsamp = K * (j + 2) + warp;     // this warp's sample
            ull pk = KEY_INF;
            if (tsamp < MAX_ITER)
                pk = scan_part(nodes_s, samps[tsamp], K * j,
                               (int)crank, CSIZE, lane);
            pk = bfly_min(pk);
            if (lane == 0) stage[obj][warp] = pk;     // local staging (slot=warp<31)
            SCAN_BAR();                               // 31 scan warps: staging visible

            // ---- batched cross-CTA send: warp w (w<8) -> CTA w, lane 0 only ----
            if (warp < CSIZE && lane == 0) {
                // backpressure: previous readers of bests[obj] (all dst serials
                // at their block j-2) must have finished before we overwrite
                if (j >= 4)
                    mbar_wait_cluster(mb_free0 + 8 * obj, ((j - 4) >> 2) & 1);
                uint32_t src  = smem_u32(&stage[obj][0]);
                uint32_t dstr = mapa_u32(smem_u32(&bests[obj][crank][0]),
                                         (uint32_t)warp);
                #pragma unroll
                for (int k = 0; k < 16; k++) {        // 32 slots = 16 x 16B
                    ull a0, a1;
                    asm volatile("ld.shared.v2.u64 {%0, %1}, [%2];"
                                 : "=l"(a0), "=l"(a1) : "r"(src + 16 * k));
                    asm volatile("st.shared::cluster.v2.u64 [%0], {%1, %2};"
                                 :: "r"(dstr + 16 * k), "l"(a0), "l"(a1) : "memory");
                }
                mbar_arrive_cluster_remote(mapa_u32(mb_bests0 + 8 * obj,
                                                    (uint32_t)warp));
            }
        }
    }

    __syncthreads();
    CLUSTER_ARRIVE();
    CLUSTER_WAIT();

    if (crank == 0) {
        const float* ns = reinterpret_cast<const float*>(nodes_s);
        for (int i = tid; i < 2 * NNODES; i += NTHREADS)
            out[i] = ns[i];
    }
}

extern "C" void kernel_launch(void* const* d_in, const int* in_sizes, int n_in,
                              void* d_out, int out_size)
{
    const float* state = (const float*)d_in[0];
    const float* goal  = (const float*)d_in[1];
    const float* u     = (const float*)d_in[2];
    const float* r     = (const float*)d_in[3];
    float* out = (float*)d_out;

    cudaFuncSetAttribute(rrt_kernel,
                         cudaFuncAttributeMaxDynamicSharedMemorySize,
                         (int)SMEM_BYTES);
    rrt_kernel<<<CSIZE, NTHREADS, SMEM_BYTES>>>(state, goal, u, r, out);
}